// round 7
// baseline (speedup 1.0000x reference)
#include <cuda_runtime.h>
#include <cstdint>

// VarConvND via tcgen05 TF32 per-location GEMM (sm_103a), SIMT fallback body
// for the plain compute_103 PTX pass (never selected at runtime on GB300).
//
//   out[b, co, s] = sum_k (unfold(X)[b, k, s] + bias[s]) * weight[s, k, co]
// Decomposed: out = unfold(X)^T @ W + bias[s] * colsum_k(W[s,:,co]).
//
// Pass 1: X (B,C,H,W) -> Xt (H,W,C,B), values pre-rounded to tf32 (rna).
// Pass 2: one block per s. M=64(pad 128) x N=64 x K=1152 tcgen05 tf32.
//         W streamed via cp.async 4-deep raw ring -> LDS -> cvt.rna -> STS.
//         A gathered from L2-resident Xt via offset table. 2-stage MMA bufs.
// Pass 3: transpose scratch (s, f) -> out (f, s).

#if defined(__CUDA_ARCH_FEAT_SM103_ALL) || defined(__CUDA_ARCH_FEAT_SM100_ALL)
#define HAS_TCGEN05 1
#else
#define HAS_TCGEN05 0
#endif

__device__ float g_Xt[32 * 32 * 128 * 64];      // 33.5 MB (tf32-rounded)
__device__ float g_scratch[1024 * 64 * 64];     // 16.8 MB

// smem layout (byte offsets from 1024-aligned base):
//   A stages   [0, 16384)        2 x 8KB
//   B stages   [16384, 32768)    2 x 8KB
//   W raw ring [32768, 65536)    4 x 8KB
//   koff       [65536, 70144)    1152 x int
//   colsum4    [70144, 71168)    4 x 64 float
//   colsum     [71168, 71424)    64 float
//   mbar       [71424, 71440)    2 x u64
//   tmem ptr   [71440, 71444)
#define SM_B    16384
#define SM_WRAW 32768
#define SM_KOFF 65536
#define SM_CS4  70144
#define SM_CS   71168
#define SM_MBAR 71424
#define SM_TPTR 71440
#define DYN_BYTES (71444 + 1024)

// ---------------------------------------------------------------------------
// helpers
// ---------------------------------------------------------------------------
__device__ __forceinline__ uint32_t smem_u32(const void* p) {
    uint32_t a;
    asm("{ .reg .u64 t; cvta.to.shared.u64 t, %1; cvt.u32.u64 %0, t; }" : "=r"(a) : "l"(p));
    return a;
}
__device__ __forceinline__ uint32_t f2tf32(float f) {
    uint32_t r;
    asm("cvt.rna.tf32.f32 %0, %1;" : "=r"(r) : "f"(f));
    return r;
}
#define SWZ(o) ((o) ^ (((o) >> 3) & 0x70))

#if HAS_TCGEN05
__device__ __forceinline__ uint32_t elect_one() {
    uint32_t p;
    asm volatile("{ .reg .pred p; elect.sync _|p, 0xFFFFFFFF; selp.b32 %0,1,0,p; }" : "=r"(p));
    return p;
}

static constexpr uint64_t DESC_BASE =
    (uint64_t(2) << 61) | (uint64_t(1) << 46) | (uint64_t(64) << 32) | (uint64_t(1) << 16);
__device__ __forceinline__ uint64_t make_desc(uint32_t addr) {
    return DESC_BASE | ((uint64_t)(addr >> 4) & 0x3FFF);
}

// idesc kind::tf32: dtype=F32(1)<<4, atype=TF32(2)<<7, btype=TF32(2)<<10,
// N=64 -> 8<<17, M=128 -> 8<<24
#define IDESC_TF32 0x8100910u

__device__ __forceinline__ void mma_tf32(uint32_t d, uint64_t ad, uint64_t bd, uint32_t en) {
    asm volatile(
        "{\n\t.reg .pred p;\n\tsetp.ne.u32 p, %4, 0;\n\t"
        "tcgen05.mma.cta_group::1.kind::tf32 [%0], %1, %2, %3, {%5,%5,%5,%5}, p;\n\t}"
        :: "r"(d), "l"(ad), "l"(bd), "r"(IDESC_TF32), "r"(en), "r"(0u) : "memory");
}

#define MBARRIER_INIT(a, c) \
    asm volatile("mbarrier.init.shared.b64 [%0], %1;" :: "r"(a), "r"(c) : "memory")

#define MBAR_WAIT(addr, ph) do { \
    uint32_t _a = (addr), _p = (ph) & 1, _d; \
    asm volatile("{\n\t.reg .pred p;\n\tmbarrier.try_wait.parity.acquire.cta.shared::cta.b64 p, [%1], %2;\n\tselp.b32 %0,1,0,p;\n\t}" \
        : "=r"(_d) : "r"(_a), "r"(_p) : "memory"); \
    while (!_d) { \
        asm volatile("{\n\t.reg .pred p;\n\tmbarrier.try_wait.parity.acquire.cta.shared::cta.b64 p, [%1], %2, 0x989680;\n\tselp.b32 %0,1,0,p;\n\t}" \
            : "=r"(_d) : "r"(_a), "r"(_p) : "memory"); \
    } \
} while (0)

#define TCG_COMMIT(mb) \
    asm volatile("tcgen05.commit.cta_group::1.mbarrier::arrive::one.shared::cluster.b64 [%0];" :: "r"(mb) : "memory")
#define TCG_ALLOC(sa, n) \
    asm volatile("tcgen05.alloc.cta_group::1.sync.aligned.shared::cta.b32 [%0], %1;" :: "r"(sa), "r"(n) : "memory")
#define TCG_DEALLOC(t, n) \
    asm volatile("tcgen05.dealloc.cta_group::1.sync.aligned.b32 %0, %1;" :: "r"(t), "r"(n))
#define TCG_RELINQ() \
    asm volatile("tcgen05.relinquish_alloc_permit.cta_group::1.sync.aligned;")
#define TCG_WAIT_LD() asm volatile("tcgen05.wait::ld.sync.aligned;" ::: "memory")
#define TCG_FENCE_AFTER() asm volatile("tcgen05.fence::after_thread_sync;" ::: "memory")

#define TCG_LD_X32(r, ta) \
    asm volatile("tcgen05.ld.sync.aligned.32x32b.x32.b32 " \
        "{%0,%1,%2,%3,%4,%5,%6,%7,%8,%9,%10,%11,%12,%13,%14,%15," \
        "%16,%17,%18,%19,%20,%21,%22,%23,%24,%25,%26,%27,%28,%29,%30,%31}, [%32];" \
        : "=r"((r)[0]), "=r"((r)[1]), "=r"((r)[2]), "=r"((r)[3]), \
          "=r"((r)[4]), "=r"((r)[5]), "=r"((r)[6]), "=r"((r)[7]), \
          "=r"((r)[8]), "=r"((r)[9]), "=r"((r)[10]), "=r"((r)[11]), \
          "=r"((r)[12]), "=r"((r)[13]), "=r"((r)[14]), "=r"((r)[15]), \
          "=r"((r)[16]), "=r"((r)[17]), "=r"((r)[18]), "=r"((r)[19]), \
          "=r"((r)[20]), "=r"((r)[21]), "=r"((r)[22]), "=r"((r)[23]), \
          "=r"((r)[24]), "=r"((r)[25]), "=r"((r)[26]), "=r"((r)[27]), \
          "=r"((r)[28]), "=r"((r)[29]), "=r"((r)[30]), "=r"((r)[31]) \
        : "r"(ta))

__device__ __forceinline__ void cp16(uint32_t dst, const void* src) {
    asm volatile("cp.async.cg.shared.global [%0], [%1], 16;" :: "r"(dst), "l"(src) : "memory");
}
#define CP_COMMIT() asm volatile("cp.async.commit_group;" ::: "memory")
#endif  // HAS_TCGEN05

// ---------------------------------------------------------------------------
// Pass 1: X (B=64, C=128, H=32, W=32) -> Xt (H, W, C, B), tf32-rounded
// ---------------------------------------------------------------------------
__global__ void __launch_bounds__(256) transpose_kernel(const float* __restrict__ X) {
    __shared__ float sm[64][33];
    const int bx = blockIdx.x;
    const int c  = bx >> 5;
    const int yy = bx & 31;
    const int t  = threadIdx.x;
    #pragma unroll
    for (int p = 0; p < 8; p++) {
        const int b = p * 8 + (t >> 5);
        const int x = t & 31;
        sm[b][x] = X[(((b * 128 + c) * 32 + yy) << 5) + x];
    }
    __syncthreads();
    #pragma unroll
    for (int q = 0; q < 8; q++) {
        const int x = q * 4 + (t >> 6);
        const int b = t & 63;
        g_Xt[((((yy << 5) + x) * 128 + c) << 6) + b] = __uint_as_float(f2tf32(sm[b][x]));
    }
}

// ---------------------------------------------------------------------------
// Pass 2: per-location GEMM
// ---------------------------------------------------------------------------
__global__ void __launch_bounds__(256) varconv_kernel(
    const float* __restrict__ W, const float* __restrict__ bias)
{
    extern __shared__ __align__(16) char dyn[];
    const uint32_t rawb = smem_u32(dyn);
    const uint32_t smb  = (rawb + 1023u) & ~1023u;
    char* smc = dyn + (smb - rawb);

    const int s = blockIdx.x;
    const int y = s >> 5, x0 = s & 31;
    const int tid = threadIdx.x;
    const float bs = bias[s];

#if HAS_TCGEN05
    const int wid = tid >> 5, lid = tid & 31;
    const int bq = tid & 63;        // batch row (A) / C_out row (B)
    const int kg = tid >> 6;        // k-subgroup 0..3 (8 k each)
    int* koff = (int*)(smc + SM_KOFF);

    const float* Wbase = W + (size_t)s * 73728;

    // --- prologue: start W ring (chunks 0..2), 2 granules x 16B per thread
    {
        const float* src0 = Wbase + tid * 4;
        #pragma unroll
        for (int ci = 0; ci < 3; ci++) {
            uint32_t dst = smb + SM_WRAW + ci * 8192 + tid * 16;
            cp16(dst, src0 + ci * 2048);
            cp16(dst + 4096, src0 + ci * 2048 + 1024);
            CP_COMMIT();
        }
    }

    if (wid == 0) { TCG_ALLOC(smb + SM_TPTR, 64); TCG_RELINQ(); }
    if (tid == 0) { MBARRIER_INIT(smb + SM_MBAR, 1); MBARRIER_INIT(smb + SM_MBAR + 8, 1); }

    // --- per-block gather-offset table
    for (int k = tid; k < 1152; k += 256) {
        const int c  = k / 9;
        const int t9 = k - c * 9;
        const int ry = t9 / 3;
        const int rx = t9 - ry * 3;
        const int yy = y + ry - 1;
        const int xc = x0 + rx - 1;
        koff[k] = (((unsigned)yy < 32u) && ((unsigned)xc < 32u))
                      ? ((((yy << 5) + xc) * 128 + c) << 6) : -1;
    }
    __syncthreads();
    uint32_t tmem;
    asm("ld.shared.b32 %0, [%1];" : "=r"(tmem) : "r"(smb + SM_TPTR));

    uint32_t av[8];
    auto loadA = [&](int ci) {
        const int kb = ci * 32 + kg * 8;
        #pragma unroll
        for (int u = 0; u < 8; u++) {
            const int off = koff[kb + u];
            float va = 0.0f;
            if (off >= 0) va = g_Xt[off + bq];
            av[u] = __float_as_uint(va);
        }
    };
    loadA(0);

    int ph0 = 0, ph1 = 0;
    float csum = 0.0f;
    const uint32_t off = (uint32_t)bq * 128 + (uint32_t)kg * 32;

    for (int i = 0; i < 36; i++) {
        const int st = i & 1;
        if (i >= 2) {
            if (st == 0) { MBAR_WAIT(smb + SM_MBAR, ph0); ph0 ^= 1; }
            else         { MBAR_WAIT(smb + SM_MBAR + 8, ph1); ph1 ^= 1; }
        }
        // A stage fill from prefetched regs
        *(uint4*)(smc + st * 8192 + SWZ(off))      = make_uint4(av[0], av[1], av[2], av[3]);
        *(uint4*)(smc + st * 8192 + SWZ(off + 16)) = make_uint4(av[4], av[5], av[6], av[7]);
        if (i + 1 < 36) loadA(i + 1);

        // W raw chunk i has landed?
        if (i < 34)      asm volatile("cp.async.wait_group 2;" ::: "memory");
        else if (i == 34) asm volatile("cp.async.wait_group 1;" ::: "memory");
        else             asm volatile("cp.async.wait_group 0;" ::: "memory");
        __syncthreads();

        // B: LDS raw -> cvt.rna -> STS swizzled; accumulate colsum
        {
            const char* wr = smc + SM_WRAW + (i & 3) * 8192 + (bq << 2) + (kg << 11);
            uint32_t bv[8];
            #pragma unroll
            for (int u = 0; u < 8; u++) {
                const float w = *(const float*)(wr + (u << 8));
                bv[u] = f2tf32(w);
                csum += __uint_as_float(bv[u]);
            }
            *(uint4*)(smc + SM_B + st * 8192 + SWZ(off))      = make_uint4(bv[0], bv[1], bv[2], bv[3]);
            *(uint4*)(smc + SM_B + st * 8192 + SWZ(off + 16)) = make_uint4(bv[4], bv[5], bv[6], bv[7]);
        }
        // refill W ring 3 ahead (overwrites stage consumed at i-1)
        if (i + 3 < 36) {
            const int ci = i + 3;
            uint32_t dst = smb + SM_WRAW + (ci & 3) * 8192 + tid * 16;
            const float* src = Wbase + ci * 2048 + tid * 4;
            cp16(dst, src);
            cp16(dst + 4096, src + 1024);
            CP_COMMIT();
        }
        asm volatile("fence.proxy.async.shared::cta;" ::: "memory");
        __syncthreads();

        if (wid == 0 && elect_one()) {
            uint64_t ad = make_desc(smb + st * 8192);
            uint64_t bd = make_desc(smb + SM_B + st * 8192);
            mma_tf32(tmem, ad,     bd,     i > 0 ? 1u : 0u);
            mma_tf32(tmem, ad + 2, bd + 2, 1u);
            mma_tf32(tmem, ad + 4, bd + 4, 1u);
            mma_tf32(tmem, ad + 6, bd + 6, 1u);
            TCG_COMMIT(smb + SM_MBAR + st * 8);
        }
    }

    // colsum reduction: colsum[co] = sum over 4 kg partials
    ((float*)(smc + SM_CS4))[kg * 64 + bq] = csum;
    __syncthreads();
    if (tid < 64) {
        const float* c4 = (const float*)(smc + SM_CS4);
        ((float*)(smc + SM_CS))[tid] = c4[tid] + c4[64 + tid] + c4[128 + tid] + c4[192 + tid];
    }
    __syncthreads();

    MBAR_WAIT(smb + SM_MBAR, ph0);
    MBAR_WAIT(smb + SM_MBAR + 8, ph1);
    TCG_FENCE_AFTER();

    if (wid < 2) {
        const float* cs = (const float*)(smc + SM_CS);
        const int b = wid * 32 + lid;
        float* dst = g_scratch + ((size_t)s * 64 + b) * 64;
        uint32_t dr[32];
        TCG_LD_X32(dr, tmem);
        TCG_WAIT_LD();
        #pragma unroll
        for (int c = 0; c < 32; c++)
            dr[c] = __float_as_uint(__uint_as_float(dr[c]) + bs * cs[c]);
        #pragma unroll
        for (int j = 0; j < 8; j++)
            ((uint4*)dst)[j] = make_uint4(dr[4 * j], dr[4 * j + 1], dr[4 * j + 2], dr[4 * j + 3]);
        TCG_LD_X32(dr, tmem + 32);
        TCG_WAIT_LD();
        #pragma unroll
        for (int c = 0; c < 32; c++)
            dr[c] = __float_as_uint(__uint_as_float(dr[c]) + bs * cs[32 + c]);
        #pragma unroll
        for (int j = 0; j < 8; j++)
            ((uint4*)(dst + 32))[j] = make_uint4(dr[4 * j], dr[4 * j + 1], dr[4 * j + 2], dr[4 * j + 3]);
    }
    __syncthreads();
    if (wid == 0) TCG_DEALLOC(tmem, 64);

#else  // ------- SIMT fallback (plain compute_103 pass; not selected on GB300)
    float (*As)[68] = (float(*)[68])smc;
    float (*Bs)[64] = (float(*)[64])(smc + 32 * 68 * 4);
    const int tx = tid & 15;
    const int ty = tid >> 4;
    const float* Wp = W + (size_t)s * 73728;

    float acc[4][4];
    #pragma unroll
    for (int i = 0; i < 4; i++)
        #pragma unroll
        for (int j = 0; j < 4; j++) acc[i][j] = 0.0f;

    for (int k0 = 0; k0 < 1152; k0 += 32) {
        {
            const float4* src = (const float4*)(Wp + k0 * 64);
            float4* dstB = (float4*)(&Bs[0][0]);
            dstB[tid]       = src[tid];
            dstB[tid + 256] = src[tid + 256];
        }
        #pragma unroll
        for (int i = 0; i < 2; i++) {
            const int kk = i * 16 + (tid >> 4);
            const int k  = k0 + kk;
            const int c   = k / 9;
            const int tap = k - c * 9;
            const int r   = tap / 3;
            const int cc  = tap - r * 3;
            const int yy = y + r - 1;
            const int xx = x0 + cc - 1;
            const int b4 = (tid & 15) << 2;
            float4 v = make_float4(0.f, 0.f, 0.f, 0.f);
            if (((unsigned)yy < 32u) && ((unsigned)xx < 32u))
                v = *(const float4*)(g_Xt + ((((yy << 5) + xx) * 128 + c) << 6) + b4);
            v.x += bs; v.y += bs; v.z += bs; v.w += bs;
            *(float4*)&As[kk][b4] = v;
        }
        __syncthreads();
        #pragma unroll
        for (int kk = 0; kk < 32; kk++) {
            const float4 a = *(const float4*)&As[kk][ty << 2];
            const float4 b = *(const float4*)&Bs[kk][tx << 2];
            acc[0][0] += a.x * b.x; acc[0][1] += a.x * b.y; acc[0][2] += a.x * b.z; acc[0][3] += a.x * b.w;
            acc[1][0] += a.y * b.x; acc[1][1] += a.y * b.y; acc[1][2] += a.y * b.z; acc[1][3] += a.y * b.w;
            acc[2][0] += a.z * b.x; acc[2][1] += a.z * b.y; acc[2][2] += a.z * b.z; acc[2][3] += a.z * b.w;
            acc[3][0] += a.w * b.x; acc[3][1] += a.w * b.y; acc[3][2] += a.w * b.z; acc[3][3] += a.w * b.w;
        }
        __syncthreads();
    }
    #pragma unroll
    for (int i = 0; i < 4; i++) {
        const int b = (ty << 2) + i;
        #pragma unroll
        for (int j = 0; j < 4; j++) {
            const int co = (tx << 2) + j;
            g_scratch[((size_t)s * 64 + b) * 64 + co] = acc[i][j];
        }
    }
#endif
}

// ---------------------------------------------------------------------------
// Pass 3: scratch (s, f) -> out (f, s), f = b*64 + co
// ---------------------------------------------------------------------------
__global__ void __launch_bounds__(256) out_transpose(float* __restrict__ out) {
    __shared__ float tile[32][33];
    const int f0 = blockIdx.x * 32;
    const int s0 = blockIdx.y * 32;
    const int tc = threadIdx.x & 31;
    const int tr = threadIdx.x >> 5;
    #pragma unroll
    for (int r = 0; r < 4; r++) {
        const int sl = tr * 4 + r;
        tile[sl][tc] = g_scratch[(size_t)(s0 + sl) * 4096 + f0 + tc];
    }
    __syncthreads();
    #pragma unroll
    for (int r = 0; r < 4; r++) {
        const int fl = tr * 4 + r;
        out[(size_t)(f0 + fl) * 1024 + s0 + tc] = tile[tc][fl];
    }
}

extern "C" void kernel_launch(void* const* d_in, const int* in_sizes, int n_in,
                              void* d_out, int out_size) {
    const float* X    = (const float*)d_in[0];
    const float* W    = (const float*)d_in[1];
    const float* bias = (const float*)d_in[2];
    float* out = (float*)d_out;

    cudaFuncSetAttribute(varconv_kernel,
                         cudaFuncAttributeMaxDynamicSharedMemorySize, DYN_BYTES);

    transpose_kernel<<<128 * 32, 256>>>(X);
    varconv_kernel<<<1024, 256, DYN_BYTES>>>(W, bias);
    out_transpose<<<dim3(128, 32), 256>>>(out);
}